// round 11
// baseline (speedup 1.0000x reference)
#include <cuda_runtime.h>

// UniSURF-style renderer: per-ray sphere intersect + 32-step occupancy march
// + 8 secant iterations on a tiny MLP (3 -> 32 -> 1). One ray per thread.
//
//   occ logit z(d) = b2 + sum_j relu(A_j + d*R_j) * W2_j
//   A_j, W_j are launch constants in SMEM (ld.shared.v2.u64, asm volatile);
//   only R_j (ray.W1) is per-ray register state. The march evaluates FOUR
//   samples per A/W load set (occ_z_quad): 16 LDS per 128 FFMA2 -> LSU well
//   below fma-pipe time, and 8 independent acc chains of ILP per warp.
//   z cached in smem; predicated first-crossing capture; 1024x64 grid with
//   warp-granular chunks (exactly 2 chunks/warp, zero divergence).

#define HID     32
#define NPAIR   16
#define NSTEPS  32
#define NSECANT 8
#define NEARV   0.5f
#define EPSV    1e-6f
#define THREADS 64
#define NBLK    1024

typedef unsigned long long ull;
typedef unsigned int uint32;

__device__ __forceinline__ ull pack2(float x, float y) {
    ull r;
    asm("mov.b64 %0, {%1, %2};" : "=l"(r) : "f"(x), "f"(y));
    return r;
}

__device__ __forceinline__ void unpack2(ull v, float& x, float& y) {
    asm("mov.b64 {%0, %1}, %2;" : "=f"(x), "=f"(y) : "l"(v));
}

__device__ __forceinline__ ull relu2(ull v) {
    float x, y;
    unpack2(v, x, y);
    return pack2(fmaxf(x, 0.0f), fmaxf(y, 0.0f));
}

__device__ __forceinline__ ull dup2(float d) {
    ull dd;
    asm("mov.b64 %0, {%1, %1};" : "=l"(dd) : "f"(d));
    return dd;
}

__device__ __forceinline__ ull fma2(ull a, ull b, ull c) {
    ull r;
    asm("fma.rn.f32x2 %0, %1, %2, %3;" : "=l"(r) : "l"(a), "l"(b), "l"(c));
    return r;
}

__device__ __forceinline__ float reduce2(ull a0, ull a1, float b2v) {
    ull s;
    asm("add.rn.f32x2 %0, %1, %2;" : "=l"(s) : "l"(a0), "l"(a1));
    float sx, sy;
    unpack2(s, sx, sy);
    return b2v + (sx + sy);
}

// load {A_pair, W_pair} from smem at byte offset OFFS (string literal)
#define LDAW(OFFS, Ak, Wk) \
    asm volatile("ld.shared.v2.u64 {%0, %1}, [%2+" OFFS "];" \
                 : "=l"(Ak), "=l"(Wk) : "r"(awb))

#define FORALL(M) M(0,"0") M(1,"16") M(2,"32") M(3,"48") M(4,"64") M(5,"80") \
    M(6,"96") M(7,"112") M(8,"128") M(9,"144") M(10,"160") M(11,"176") \
    M(12,"192") M(13,"208") M(14,"224") M(15,"240")

// single eval: z(d). 2 acc chains.
__device__ __forceinline__ float occ_z(float d, const ull* R, uint32 awb,
                                       float b2v) {
    const ull dd = dup2(d);
    ull a0 = 0ull, a1 = 0ull;
#define SSTEP(K, OFFS) { \
    ull Ak, Wk; LDAW(OFFS, Ak, Wk); \
    ull h = relu2(fma2(dd, R[K], Ak)); \
    if ((K) & 1) a1 = fma2(h, Wk, a1); else a0 = fma2(h, Wk, a0); }
    FORALL(SSTEP)
#undef SSTEP
    return reduce2(a0, a1, b2v);
}

// dual eval: z(da), z(db); A/W loads shared; 4 indep chains.
__device__ __forceinline__ void occ_z_dual(float da, float db, const ull* R,
                                           uint32 awb, float b2v,
                                           float& za, float& zb) {
    const ull dda = dup2(da);
    const ull ddb = dup2(db);
    ull a0 = 0ull, a1 = 0ull, b0 = 0ull, b1 = 0ull;
#define DSTEP(K, OFFS) { \
    ull Ak, Wk; LDAW(OFFS, Ak, Wk); \
    ull ha = relu2(fma2(dda, R[K], Ak)); \
    ull hb = relu2(fma2(ddb, R[K], Ak)); \
    if ((K) & 1) { a1 = fma2(ha, Wk, a1); b1 = fma2(hb, Wk, b1); } \
    else         { a0 = fma2(ha, Wk, a0); b0 = fma2(hb, Wk, b0); } }
    FORALL(DSTEP)
#undef DSTEP
    za = reduce2(a0, a1, b2v);
    zb = reduce2(b0, b1, b2v);
}

// quad eval: z(d0..d3); A/W loads amortized over 4 samples; 8 indep chains.
__device__ __forceinline__ void occ_z_quad(float d0, float d1, float d2,
                                           float d3, const ull* R, uint32 awb,
                                           float b2v, float* z) {
    const ull dd0 = dup2(d0);
    const ull dd1 = dup2(d1);
    const ull dd2 = dup2(d2);
    const ull dd3 = dup2(d3);
    ull q0[4] = {0ull, 0ull, 0ull, 0ull};  // even-pair chains, samples 0..3
    ull q1[4] = {0ull, 0ull, 0ull, 0ull};  // odd-pair chains,  samples 0..3
#define QSTEP(K, OFFS) { \
    ull Ak, Wk; LDAW(OFFS, Ak, Wk); \
    ull h0 = relu2(fma2(dd0, R[K], Ak)); \
    ull h1 = relu2(fma2(dd1, R[K], Ak)); \
    ull h2 = relu2(fma2(dd2, R[K], Ak)); \
    ull h3 = relu2(fma2(dd3, R[K], Ak)); \
    if ((K) & 1) { \
        q1[0] = fma2(h0, Wk, q1[0]); q1[1] = fma2(h1, Wk, q1[1]); \
        q1[2] = fma2(h2, Wk, q1[2]); q1[3] = fma2(h3, Wk, q1[3]); \
    } else { \
        q0[0] = fma2(h0, Wk, q0[0]); q0[1] = fma2(h1, Wk, q0[1]); \
        q0[2] = fma2(h2, Wk, q0[2]); q0[3] = fma2(h3, Wk, q0[3]); } }
    FORALL(QSTEP)
#undef QSTEP
    z[0] = reduce2(q0[0], q1[0], b2v);
    z[1] = reduce2(q0[1], q1[1], b2v);
    z[2] = reduce2(q0[2], q1[2], b2v);
    z[3] = reduce2(q0[3], q1[3], b2v);
}

__device__ __forceinline__ float sigmoidf_(float z) {
    return 1.0f / (1.0f + __expf(-z));
}

__global__ void __launch_bounds__(THREADS, 8) unisurf_kernel(
    const float* __restrict__ cam, const float* __restrict__ dirs,
    const float* __restrict__ W1, const float* __restrict__ b1,
    const float* __restrict__ W2, const float* __restrict__ b2,
    float* __restrict__ out, int P)
{
    __shared__ float sW1[3][HID];
    __shared__ __align__(16) float sAW[NPAIR * 4];  // {A0,A1,W0,W1} x16
    __shared__ float sMisc[5];                       // cam0..2, b2, |cam|^2
    __shared__ float zbuf[NSTEPS][THREADS];          // march z cache

    const int tid = threadIdx.x;
    if (tid < HID) {
        const float c0 = cam[0], c1 = cam[1], c2 = cam[2];
        const float w0 = W1[tid], w1 = W1[HID + tid], w2 = W1[2 * HID + tid];
        sW1[0][tid] = w0;
        sW1[1][tid] = w1;
        sW1[2][tid] = w2;
        const float Aj = fmaf(c0, w0, fmaf(c1, w1, fmaf(c2, w2, b1[tid])));
        const int k = tid >> 1, h = tid & 1;
        sAW[k * 4 + h] = Aj;
        sAW[k * 4 + 2 + h] = W2[tid];
        if (tid == 0) {
            sMisc[0] = c0; sMisc[1] = c1; sMisc[2] = c2;
            sMisc[3] = b2[0];
            sMisc[4] = c0 * c0 + c1 * c1 + c2 * c2;
        }
    }
    __syncthreads();

    uint32 awb;
    asm("{ .reg .u64 t; cvta.to.shared.u64 t, %1; cvt.u32.u64 %0, t; }"
        : "=r"(awb) : "l"(sAW));

    const float c0 = sMisc[0], c1 = sMisc[1], c2 = sMisc[2];
    const float b2v = sMisc[3], cc = sMisc[4];
    const float stepc = 1.0f / (float)(NSTEPS - 1);

    // warp-granular chunks of 32 rays; 2048 warps x exactly 2 chunks.
    const int lane = tid & 31;
    const int gw = blockIdx.x * (THREADS / 32) + (tid >> 5);
    const int totalw = gridDim.x * (THREADS / 32);
    const int nchunks = (P + 31) >> 5;

    for (int c = gw; c < nchunks; c += totalw) {
        const int p = (c << 5) + lane;
        const int pc = p < P ? p : (P - 1);

        const float dx = dirs[3 * pc + 0];
        const float dy = dirs[3 * pc + 1];
        const float dz = dirs[3 * pc + 2];
        const float invn = rsqrtf(dx * dx + dy * dy + dz * dz);
        const float rx = dx * invn, ry = dy * invn, rz = dz * invn;

        const float rcd = rx * c0 + ry * c1 + rz * c2;
        const float under = rcd * rcd - (cc - 1.0f);   // radius = 1
        const bool hit = under > 0.0f;
        const float s = sqrtf(fmaxf(under, 0.0f));
        const float far = fmaxf(s - rcd, NEARV + EPSV);
        const float stepd = (far - NEARV) * stepc;     // incremental step

        // per-ray R_j = ray.W1_j (only per-ray MLP state)
        ull R[NPAIR];
#pragma unroll
        for (int k = 0; k < NPAIR; k++) {
            const int j = 2 * k;
            const float r0 = fmaf(rx, sW1[0][j],
                             fmaf(ry, sW1[1][j], rz * sW1[2][j]));
            const float r1 = fmaf(rx, sW1[0][j + 1],
                             fmaf(ry, sW1[1][j + 1], rz * sW1[2][j + 1]));
            R[k] = pack2(r0, r1);
        }

        // coarse march: sample 0, then 7 quads (1..28), dual (29,30),
        // single (31). z cached in smem; predicated first-crossing capture.
        int  idx = 0;
        bool found = false;
        float zprev = occ_z(NEARV, R, awb, b2v);
        zbuf[0][tid] = zprev;
        float d = NEARV;
#pragma unroll 1
        for (int i = 1; i <= 25; i += 4) {   // i = 1,5,...,25: samples i..i+3
            const float d0 = d + stepd;
            const float d1 = d0 + stepd;
            const float d2 = d1 + stepd;
            const float d3 = d2 + stepd;
            float z[4];
            occ_z_quad(d0, d1, d2, d3, R, awb, b2v, z);
            zbuf[i][tid] = z[0];
            zbuf[i + 1][tid] = z[1];
            zbuf[i + 2][tid] = z[2];
            zbuf[i + 3][tid] = z[3];
            const bool cr0 = (zprev < 0.0f) && (z[0] >= 0.0f);
            const bool cr1 = (z[0] < 0.0f) && (z[1] >= 0.0f);
            const bool cr2 = (z[1] < 0.0f) && (z[2] >= 0.0f);
            const bool cr3 = (z[2] < 0.0f) && (z[3] >= 0.0f);
            idx = (!found && cr0) ? (i - 1) : idx;  found |= cr0;
            idx = (!found && cr1) ? (i + 0) : idx;  found |= cr1;
            idx = (!found && cr2) ? (i + 1) : idx;  found |= cr2;
            idx = (!found && cr3) ? (i + 2) : idx;  found |= cr3;
            zprev = z[3];
            d = d3;
        }
        {   // samples 29,30 (dual)
            const float da = d + stepd;
            const float db = da + stepd;
            float za, zb;
            occ_z_dual(da, db, R, awb, b2v, za, zb);
            zbuf[29][tid] = za;
            zbuf[30][tid] = zb;
            const bool ca = (zprev < 0.0f) && (za >= 0.0f);
            const bool cb = (za < 0.0f) && (zb >= 0.0f);
            idx = (!found && ca) ? 28 : idx;  found |= ca;
            idx = (!found && cb) ? 29 : idx;  found |= cb;
            zprev = zb;
            d = db;
        }
        {   // sample 31 (single)
            const float dcur = d + stepd;
            const float z = occ_z(dcur, R, awb, b2v);
            zbuf[31][tid] = z;
            const bool cl = (zprev < 0.0f) && (z >= 0.0f);
            idx = (!found && cl) ? 30 : idx;
            found |= cl;
        }

        float dpred = 0.0f, osurf = 0.0f;
        const bool ok = found && hit;

        if (ok) {
            // brackets via the exact reference formula; z from the cache
            const float tl = (float)idx * stepc;
            const float th = (float)(idx + 1) * stepc;
            float dl = fmaf(far, tl, NEARV * (1.0f - tl));
            float dh = fmaf(far, th, NEARV * (1.0f - th));
            float fl = sigmoidf_(zbuf[idx][tid]) - 0.5f;
            float fh = sigmoidf_(zbuf[idx + 1][tid]) - 0.5f;

#pragma unroll 1
            for (int it = 0; it < NSECANT; it++) {
                float den = fh - fl;
                if (fabsf(den) < EPSV) den = EPSV;
                const float dm = dl - __fdividef(fl * (dh - dl), den);
                const float fm = sigmoidf_(occ_z(dm, R, awb, b2v)) - 0.5f;
                if (fm < 0.0f) { dl = dm; fl = fm; }
                else           { dh = dm; fh = fm; }
            }
            float den = fh - fl;
            if (fabsf(den) < EPSV) den = EPSV;
            dpred = dl - __fdividef(fl * (dh - dl), den);
            osurf = sigmoidf_(occ_z(dpred, R, awb, b2v));
        }

        if (p < P) {
            out[p] = dpred;
            out[P + p] = osurf;
        }
    }
}

extern "C" void kernel_launch(void* const* d_in, const int* in_sizes, int n_in,
                              void* d_out, int out_size)
{
    const float* cam  = (const float*)d_in[0];
    const float* dirs = (const float*)d_in[1];
    const float* W1   = (const float*)d_in[2];
    const float* b1   = (const float*)d_in[3];
    const float* W2   = (const float*)d_in[4];
    const float* b2   = (const float*)d_in[5];
    float* out = (float*)d_out;

    const int P = in_sizes[1] / 3;
    const int nchunks = (P + 31) >> 5;
    int blocks = NBLK;
    const int maxb = (nchunks + 1) / 2;   // 2 warps per block
    if (blocks > maxb) blocks = maxb;
    if (blocks < 1) blocks = 1;
    unisurf_kernel<<<blocks, THREADS>>>(cam, dirs, W1, b1, W2, b2, out, P);
}

// round 13
// speedup vs baseline: 1.1705x; 1.1705x over previous
#include <cuda_runtime.h>

// UniSURF renderer, piecewise-linear prefix march.
//
// z(d) = b2 + sum_j W_j relu(A_j + d R_j)
//      = K0 + K1 d + sum_j U_j |d - t_j| ,  U_j = 0.5 W_j |R_j|, t_j = -A_j/R_j
// Per ray: bucket each unit's breakpoint into its march segment (no sort),
// then each march sample costs ~4 FMA (running alpha/beta prefix) instead of
// a full 32-unit MLP eval. Secant keeps full evals (A/W in smem via LDAW,
// R in registers, packed f32x2). zbuf caches march z for secant brackets.

#define HID     32
#define NPAIR   16
#define NSTEPS  32
#define NSECANT 8
#define NEARV   0.5f
#define EPSV    1e-6f
#define RTINY   1e-30f
#define THREADS 64
#define NBLK    1024

typedef unsigned long long ull;
typedef unsigned int uint32;

__device__ __forceinline__ ull pack2(float x, float y) {
    ull r;
    asm("mov.b64 %0, {%1, %2};" : "=l"(r) : "f"(x), "f"(y));
    return r;
}

__device__ __forceinline__ void unpack2(ull v, float& x, float& y) {
    asm("mov.b64 {%0, %1}, %2;" : "=f"(x), "=f"(y) : "l"(v));
}

__device__ __forceinline__ ull relu2(ull v) {
    float x, y;
    unpack2(v, x, y);
    return pack2(fmaxf(x, 0.0f), fmaxf(y, 0.0f));
}

__device__ __forceinline__ ull dup2(float d) {
    ull dd;
    asm("mov.b64 %0, {%1, %1};" : "=l"(dd) : "f"(d));
    return dd;
}

__device__ __forceinline__ ull fma2(ull a, ull b, ull c) {
    ull r;
    asm("fma.rn.f32x2 %0, %1, %2, %3;" : "=l"(r) : "l"(a), "l"(b), "l"(c));
    return r;
}

__device__ __forceinline__ float reduce2(ull a0, ull a1, float b2v) {
    ull s;
    asm("add.rn.f32x2 %0, %1, %2;" : "=l"(s) : "l"(a0), "l"(a1));
    float sx, sy;
    unpack2(s, sx, sy);
    return b2v + (sx + sy);
}

#define LDAW(OFFS, Ak, Wk) \
    asm volatile("ld.shared.v2.u64 {%0, %1}, [%2+" OFFS "];" \
                 : "=l"(Ak), "=l"(Wk) : "r"(awb))

#define FORALL(M) M(0,"0") M(1,"16") M(2,"32") M(3,"48") M(4,"64") M(5,"80") \
    M(6,"96") M(7,"112") M(8,"128") M(9,"144") M(10,"160") M(11,"176") \
    M(12,"192") M(13,"208") M(14,"224") M(15,"240")

// full MLP eval (secant path): 2 acc chains, A/W from smem.
__device__ __forceinline__ float occ_z(float d, const ull* R, uint32 awb,
                                       float b2v) {
    const ull dd = dup2(d);
    ull a0 = 0ull, a1 = 0ull;
#define SSTEP(K, OFFS) { \
    ull Ak, Wk; LDAW(OFFS, Ak, Wk); \
    ull h = relu2(fma2(dd, R[K], Ak)); \
    if ((K) & 1) a1 = fma2(h, Wk, a1); else a0 = fma2(h, Wk, a0); }
    FORALL(SSTEP)
#undef SSTEP
    return reduce2(a0, a1, b2v);
}

__device__ __forceinline__ float sigmoidf_(float z) {
    return 1.0f / (1.0f + __expf(-z));
}

__global__ void __launch_bounds__(THREADS, 8) unisurf_kernel(
    const float* __restrict__ cam, const float* __restrict__ dirs,
    const float* __restrict__ W1, const float* __restrict__ b1,
    const float* __restrict__ W2, const float* __restrict__ b2,
    float* __restrict__ out, int P)
{
    __shared__ float sW1[3][HID];
    __shared__ __align__(16) float sAW[NPAIR * 4];  // {A0,A1,W0,W1} x16 (secant)
    __shared__ float sA[HID];                        // A_j
    __shared__ float sV[HID];                        // 0.5 * W2_j
    __shared__ float sVA[HID];                       // 0.5 * W2_j * |A_j|
    __shared__ float sMisc[6];                       // cam0..2, b2, |cam|^2, K0
    __shared__ ull   bPQ[NSTEPS][THREADS];           // bucket (U, U*t) pairs
    __shared__ float zbuf[NSTEPS][THREADS];          // march z cache

    const int tid = threadIdx.x;
    if (tid < HID) {
        const float c0 = cam[0], c1 = cam[1], c2 = cam[2];
        const float w0 = W1[tid], w1 = W1[HID + tid], w2 = W1[2 * HID + tid];
        sW1[0][tid] = w0;
        sW1[1][tid] = w1;
        sW1[2][tid] = w2;
        const float Aj = fmaf(c0, w0, fmaf(c1, w1, fmaf(c2, w2, b1[tid])));
        const float Wj = W2[tid];
        const int k = tid >> 1, h = tid & 1;
        sAW[k * 4 + h] = Aj;
        sAW[k * 4 + 2 + h] = Wj;
        sA[tid] = Aj;
        sV[tid] = 0.5f * Wj;
        sVA[tid] = 0.5f * Wj * fabsf(Aj);
        if (tid == 0) {
            sMisc[0] = c0; sMisc[1] = c1; sMisc[2] = c2;
            sMisc[3] = b2[0];
            sMisc[4] = c0 * c0 + c1 * c1 + c2 * c2;
        }
    }
    __syncthreads();
    if (tid == 0) {   // K0 = b2 + sum_j 0.5 W_j A_j  (launch constant)
        float k0 = sMisc[3];
        for (int j = 0; j < HID; j++) k0 = fmaf(sV[j], sA[j], k0);
        sMisc[5] = k0;
    }
    __syncthreads();

    uint32 awb;
    asm("{ .reg .u64 t; cvta.to.shared.u64 t, %1; cvt.u32.u64 %0, t; }"
        : "=r"(awb) : "l"(sAW));

    const float c0 = sMisc[0], c1 = sMisc[1], c2 = sMisc[2];
    const float b2v = sMisc[3], cc = sMisc[4], K0 = sMisc[5];
    const float stepc = 1.0f / (float)(NSTEPS - 1);

    const int lane = tid & 31;
    const int gw = blockIdx.x * (THREADS / 32) + (tid >> 5);
    const int totalw = gridDim.x * (THREADS / 32);
    const int nchunks = (P + 31) >> 5;

    for (int c = gw; c < nchunks; c += totalw) {
        const int p = (c << 5) + lane;
        const int pc = p < P ? p : (P - 1);

        const float dx = dirs[3 * pc + 0];
        const float dy = dirs[3 * pc + 1];
        const float dz = dirs[3 * pc + 2];
        const float invn = rsqrtf(dx * dx + dy * dy + dz * dz);
        const float rx = dx * invn, ry = dy * invn, rz = dz * invn;

        const float rcd = rx * c0 + ry * c1 + rz * c2;
        const float under = rcd * rcd - (cc - 1.0f);   // radius = 1
        const bool hit = under > 0.0f;
        const float s = sqrtf(fmaxf(under, 0.0f));
        const float far = fmaxf(s - rcd, NEARV + EPSV);
        const float stepd = (far - NEARV) * stepc;
        const float invstep = __fdividef(1.0f, stepd);
        const float nfbias = -NEARV * invstep;

        // zero buckets (per-thread column; no cross-thread sharing)
#pragma unroll
        for (int k = 1; k < NSTEPS; k++) bPQ[k][tid] = 0ull;

        // per-unit setup: R_j, breakpoint bucketing, alpha/beta init
        float alpha = K0;
        float beta = 0.0f;
        ull R[NPAIR];
#pragma unroll 1
        for (int k2 = 0; k2 < NPAIR; k2++) {
            const int j = 2 * k2;
            float rr[2];
            rr[0] = fmaf(rx, sW1[0][j],
                    fmaf(ry, sW1[1][j], rz * sW1[2][j]));
            rr[1] = fmaf(rx, sW1[0][j + 1],
                    fmaf(ry, sW1[1][j + 1], rz * sW1[2][j + 1]));
            R[k2] = pack2(rr[0], rr[1]);
#pragma unroll
            for (int h = 0; h < 2; h++) {
                const int jj = j + h;
                const float rj = rr[h];
                const float aj = sA[jj];
                const bool tiny = fabsf(rj) < RTINY;
                float t = __fdividef(-aj, rj);
                t = tiny ? 0.0f : t;
                const float U = sV[jj] * fabsf(rj);
                const float Ut = U * t;
                const float nf = fmaf(t, invstep, nfbias);
                beta += (rj < 0.0f) ? (-2.0f * U) : 0.0f;
                alpha += Ut;
                alpha += tiny ? sVA[jj] : 0.0f;
                if (nf <= 0.0f) {           // breakpoint at/below near
                    beta = fmaf(2.0f, U, beta);
                    alpha = fmaf(-2.0f, Ut, alpha);
                } else if (nf <= 31.0f) {   // breakpoint inside march range
                    const int kb = __float2int_ru(nf);  // 1..31
                    float bp, bq;
                    unpack2(bPQ[kb][tid], bp, bq);
                    bPQ[kb][tid] = pack2(bp + U, bq + Ut);
                }
            }
        }

        // march: z_k = alpha_k + beta_k * d_k via prefix over buckets
        float d = NEARV;
        float zprev = fmaf(beta, d, alpha);
        zbuf[0][tid] = zprev;
        int idx = 0;
        bool found = false;
        ull pf1 = bPQ[1][tid];
        ull pf2 = bPQ[2][tid];
#pragma unroll 1
        for (int k = 1; k <= NSTEPS - 3; k++) {   // k = 1..29
            const ull cur = pf1;
            pf1 = pf2;
            pf2 = bPQ[k + 2][tid];
            float bp, bq;
            unpack2(cur, bp, bq);
            beta = fmaf(2.0f, bp, beta);
            alpha = fmaf(-2.0f, bq, alpha);
            d += stepd;
            const float z = fmaf(beta, d, alpha);
            zbuf[k][tid] = z;
            const bool cr = (zprev < 0.0f) && (z >= 0.0f);
            idx = (!found && cr) ? (k - 1) : idx;
            found |= cr;
            zprev = z;
        }
#pragma unroll
        for (int k = NSTEPS - 2; k <= NSTEPS - 1; k++) {  // k = 30, 31
            const ull cur = (k == NSTEPS - 2) ? pf1 : pf2;
            float bp, bq;
            unpack2(cur, bp, bq);
            beta = fmaf(2.0f, bp, beta);
            alpha = fmaf(-2.0f, bq, alpha);
            d += stepd;
            const float z = fmaf(beta, d, alpha);
            zbuf[k][tid] = z;
            const bool cr = (zprev < 0.0f) && (z >= 0.0f);
            idx = (!found && cr) ? (k - 1) : idx;
            found |= cr;
            zprev = z;
        }

        float dpred = 0.0f, osurf = 0.0f;
        const bool ok = found && hit;

        if (ok) {
            const float tl = (float)idx * stepc;
            const float th = (float)(idx + 1) * stepc;
            float dl = fmaf(far, tl, NEARV * (1.0f - tl));
            float dh = fmaf(far, th, NEARV * (1.0f - th));
            float fl = sigmoidf_(zbuf[idx][tid]) - 0.5f;
            float fh = sigmoidf_(zbuf[idx + 1][tid]) - 0.5f;

#pragma unroll 1
            for (int it = 0; it < NSECANT; it++) {
                float den = fh - fl;
                if (fabsf(den) < EPSV) den = EPSV;
                const float dm = dl - __fdividef(fl * (dh - dl), den);
                const float fm = sigmoidf_(occ_z(dm, R, awb, b2v)) - 0.5f;
                if (fm < 0.0f) { dl = dm; fl = fm; }
                else           { dh = dm; fh = fm; }
            }
            float den = fh - fl;
            if (fabsf(den) < EPSV) den = EPSV;
            dpred = dl - __fdividef(fl * (dh - dl), den);
            osurf = sigmoidf_(occ_z(dpred, R, awb, b2v));
        }

        if (p < P) {
            out[p] = dpred;
            out[P + p] = osurf;
        }
    }
}

extern "C" void kernel_launch(void* const* d_in, const int* in_sizes, int n_in,
                              void* d_out, int out_size)
{
    const float* cam  = (const float*)d_in[0];
    const float* dirs = (const float*)d_in[1];
    const float* W1   = (const float*)d_in[2];
    const float* b1   = (const float*)d_in[3];
    const float* W2   = (const float*)d_in[4];
    const float* b2   = (const float*)d_in[5];
    float* out = (float*)d_out;

    const int P = in_sizes[1] / 3;
    const int nchunks = (P + 31) >> 5;
    int blocks = NBLK;
    const int maxb = (nchunks + 1) / 2;   // 2 warps per block
    if (blocks > maxb) blocks = maxb;
    if (blocks < 1) blocks = 1;
    unisurf_kernel<<<blocks, THREADS>>>(cam, dirs, W1, b1, W2, b2, out, P);
}

// round 14
// speedup vs baseline: 1.1776x; 1.0061x over previous
#include <cuda_runtime.h>

// UniSURF renderer, piecewise-linear prefix march + bracket-local secant.
//
// z(d) = b2 + sum_j W_j relu(A_j + d R_j) = K0 + K1 d + sum_j U_j |d - t_j|
// March: bucket breakpoints (no sort), running alpha/beta prefix -> ~4 FMA
// per sample. At the first free->occupied crossing, capture (aL,bL,zl,zh,idx)
// in registers. Secant: z within the bracket = aL + bL*dm + corrections from
// ONLY the units bucketed into segment idx+1 (captured once, avg ~1 unit) ->
// each secant eval costs ~6 ops instead of a full 32-unit MLP pass.

#define HID     32
#define NPAIR   16
#define NSTEPS  32
#define NSECANT 8
#define NEARV   0.5f
#define EPSV    1e-6f
#define RTINY   1e-30f
#define THREADS 64
#define NCAP    8

typedef unsigned long long ull;
typedef unsigned int uint32;

__device__ __forceinline__ ull pack2(float x, float y) {
    ull r;
    asm("mov.b64 %0, {%1, %2};" : "=l"(r) : "f"(x), "f"(y));
    return r;
}

__device__ __forceinline__ void unpack2(ull v, float& x, float& y) {
    asm("mov.b64 {%0, %1}, %2;" : "=f"(x), "=f"(y) : "l"(v));
}

__device__ __forceinline__ float sigmoidf_(float z) {
    return 1.0f / (1.0f + __expf(-z));
}

// bracket-local eval: prefix line + captured breakpoint corrections
__device__ __forceinline__ float zeval_bracket(float dm, float aL, float bL,
                                               int cnt, uint32 negmask,
                                               const ull* col) {
    float z = fmaf(bL, dm, aL);
#pragma unroll 1
    for (int q = 0; q < cnt; q++) {
        float Pv, Qv;
        unpack2(col[q * THREADS], Pv, Qv);
        const float e = fmaf(Qv, dm, Pv);
        z += ((negmask >> q) & 1u) ? fminf(e, 0.0f) : fmaxf(e, 0.0f);
    }
    return z;
}

// full MLP eval (overflow fallback; rare)
__device__ __forceinline__ float zfull(float dm, float rx, float ry, float rz,
                                       const float* w1x, const float* w1y,
                                       const float* w1z, const float* sA,
                                       const float* sV, float b2v) {
    float z = b2v;
#pragma unroll
    for (int j = 0; j < HID; j++) {
        const float r = fmaf(rx, w1x[j], fmaf(ry, w1y[j], rz * w1z[j]));
        const float pre = fmaf(dm, r, sA[j]);
        z = fmaf(2.0f * sV[j], fmaxf(pre, 0.0f), z);
    }
    return z;
}

__global__ void __launch_bounds__(THREADS, 12) unisurf_kernel(
    const float* __restrict__ cam, const float* __restrict__ dirs,
    const float* __restrict__ W1, const float* __restrict__ b1,
    const float* __restrict__ W2, const float* __restrict__ b2,
    float* __restrict__ out, int P)
{
    __shared__ float sW1[3][HID];
    __shared__ float sA[HID];                 // A_j
    __shared__ float sV[HID];                 // 0.5 * W2_j
    __shared__ float sVA[HID];                // 0.5 * W2_j * |A_j|
    __shared__ float sMisc[6];                // cam0..2, b2, |cam|^2, K0
    __shared__ ull   bPQ[NSTEPS][THREADS];    // buckets; rows 0..7 reused
                                              // post-march for captures

    const int tid = threadIdx.x;
    if (tid < HID) {
        const float c0 = cam[0], c1 = cam[1], c2 = cam[2];
        const float w0 = W1[tid], w1 = W1[HID + tid], w2 = W1[2 * HID + tid];
        sW1[0][tid] = w0;
        sW1[1][tid] = w1;
        sW1[2][tid] = w2;
        const float Aj = fmaf(c0, w0, fmaf(c1, w1, fmaf(c2, w2, b1[tid])));
        const float Wj = W2[tid];
        sA[tid] = Aj;
        sV[tid] = 0.5f * Wj;
        sVA[tid] = 0.5f * Wj * fabsf(Aj);
        if (tid == 0) {
            sMisc[0] = c0; sMisc[1] = c1; sMisc[2] = c2;
            sMisc[3] = b2[0];
            sMisc[4] = c0 * c0 + c1 * c1 + c2 * c2;
        }
    }
    __syncthreads();
    if (tid == 0) {   // K0 = b2 + sum_j 0.5 W_j A_j
        float k0 = sMisc[3];
        for (int j = 0; j < HID; j++) k0 = fmaf(sV[j], sA[j], k0);
        sMisc[5] = k0;
    }
    __syncthreads();

    const int p = blockIdx.x * THREADS + tid;
    if (p >= P) return;

    const float c0 = sMisc[0], c1 = sMisc[1], c2 = sMisc[2];
    const float b2v = sMisc[3], cc = sMisc[4], K0 = sMisc[5];
    const float stepc = 1.0f / (float)(NSTEPS - 1);

    const float dx = dirs[3 * p + 0];
    const float dy = dirs[3 * p + 1];
    const float dz = dirs[3 * p + 2];
    const float invn = rsqrtf(dx * dx + dy * dy + dz * dz);
    const float rx = dx * invn, ry = dy * invn, rz = dz * invn;

    const float rcd = rx * c0 + ry * c1 + rz * c2;
    const float under = rcd * rcd - (cc - 1.0f);   // radius = 1
    const bool hit = under > 0.0f;
    const float s = sqrtf(fmaxf(under, 0.0f));
    const float far = fmaxf(s - rcd, NEARV + EPSV);
    const float stepd = (far - NEARV) * stepc;
    const float invstep = __fdividef(1.0f, stepd);
    const float nfbias = -NEARV * invstep;

    // zero buckets (per-thread column)
#pragma unroll
    for (int k = 1; k < NSTEPS; k++) bPQ[k][tid] = 0ull;

    // per-unit setup: breakpoint bucketing, alpha/beta init
    float alpha = K0;
    float beta = 0.0f;
#pragma unroll 1
    for (int k2 = 0; k2 < NPAIR; k2++) {
        const int j = 2 * k2;
        float rr[2];
        rr[0] = fmaf(rx, sW1[0][j], fmaf(ry, sW1[1][j], rz * sW1[2][j]));
        rr[1] = fmaf(rx, sW1[0][j + 1],
                fmaf(ry, sW1[1][j + 1], rz * sW1[2][j + 1]));
#pragma unroll
        for (int h = 0; h < 2; h++) {
            const int jj = j + h;
            const float rj = rr[h];
            const float aj = sA[jj];
            const bool tiny = fabsf(rj) < RTINY;
            float t = __fdividef(-aj, rj);
            t = tiny ? 0.0f : t;
            const float U = sV[jj] * fabsf(rj);
            const float Ut = U * t;
            const float nf = fmaf(t, invstep, nfbias);
            beta += (rj < 0.0f) ? (-2.0f * U) : 0.0f;
            alpha += Ut;
            alpha += tiny ? sVA[jj] : 0.0f;
            if (nf <= 0.0f) {           // breakpoint at/below near
                beta = fmaf(2.0f, U, beta);
                alpha = fmaf(-2.0f, Ut, alpha);
            } else if (nf <= 31.0f) {   // breakpoint inside march range
                const int kb = __float2int_ru(nf);  // 1..31
                float bp, bq;
                unpack2(bPQ[kb][tid], bp, bq);
                bPQ[kb][tid] = pack2(bp + U, bq + Ut);
            }
        }
    }

    // march with register capture of the crossing bracket state
    float d = NEARV;
    float zprev = fmaf(beta, d, alpha);
    int idx = 0;
    bool found = false;
    float aL = 0.0f, bL = 0.0f, zl = 0.0f, zh = 0.0f;
    ull pf1 = bPQ[1][tid];
    ull pf2 = bPQ[2][tid];
#pragma unroll 1
    for (int k = 1; k <= NSTEPS - 3; k++) {   // k = 1..29
        const ull cur = pf1;
        pf1 = pf2;
        pf2 = bPQ[k + 2][tid];
        float bp, bq;
        unpack2(cur, bp, bq);
        const float aprev = alpha, bprev = beta;
        beta = fmaf(2.0f, bp, beta);
        alpha = fmaf(-2.0f, bq, alpha);
        d += stepd;
        const float z = fmaf(beta, d, alpha);
        const bool cross = (zprev < 0.0f) && (z >= 0.0f);
        const bool take = cross && !found;
        idx = take ? (k - 1) : idx;
        aL = take ? aprev : aL;
        bL = take ? bprev : bL;
        zl = take ? zprev : zl;
        zh = take ? z : zh;
        found |= cross;
        zprev = z;
    }
#pragma unroll
    for (int k = NSTEPS - 2; k <= NSTEPS - 1; k++) {  // k = 30, 31
        const ull cur = (k == NSTEPS - 2) ? pf1 : pf2;
        float bp, bq;
        unpack2(cur, bp, bq);
        const float aprev = alpha, bprev = beta;
        beta = fmaf(2.0f, bp, beta);
        alpha = fmaf(-2.0f, bq, alpha);
        d += stepd;
        const float z = fmaf(beta, d, alpha);
        const bool cross = (zprev < 0.0f) && (z >= 0.0f);
        const bool take = cross && !found;
        idx = take ? (k - 1) : idx;
        aL = take ? aprev : aL;
        bL = take ? bprev : bL;
        zl = take ? zprev : zl;
        zh = take ? z : zh;
        found |= cross;
        zprev = z;
    }

    float dpred = 0.0f, osurf = 0.0f;
    const bool ok = found && hit;

    if (ok) {
        // capture pass: replay the EXACT setup bucketing computation and
        // collect units whose breakpoint lands in bucket idx+1.
        int cnt = 0;
        uint32 negmask = 0u;
        bool ovf = false;
        const int kbwant = idx + 1;
#pragma unroll 1
        for (int k2 = 0; k2 < NPAIR; k2++) {
            const int j = 2 * k2;
            float rr[2];
            rr[0] = fmaf(rx, sW1[0][j], fmaf(ry, sW1[1][j], rz * sW1[2][j]));
            rr[1] = fmaf(rx, sW1[0][j + 1],
                    fmaf(ry, sW1[1][j + 1], rz * sW1[2][j + 1]));
#pragma unroll
            for (int h = 0; h < 2; h++) {
                const int jj = j + h;
                const float rj = rr[h];
                const float aj = sA[jj];
                const bool tiny = fabsf(rj) < RTINY;
                float t = __fdividef(-aj, rj);
                t = tiny ? 0.0f : t;
                const float nf = fmaf(t, invstep, nfbias);
                if (!(nf <= 0.0f) && (nf <= 31.0f) &&
                    (__float2int_ru(nf) == kbwant)) {
                    if (cnt < NCAP) {
                        const float w = 2.0f * sV[jj];
                        const float sgn = (rj < 0.0f) ? -1.0f : 1.0f;
                        bPQ[cnt][tid] = pack2(w * sgn * aj, w * sgn * rj);
                        negmask |= (w < 0.0f ? 1u : 0u) << cnt;
                        cnt++;
                    } else {
                        ovf = true;
                    }
                }
            }
        }

        const ull* col = &bPQ[0][tid];
        const float tl = (float)idx * stepc;
        const float th = (float)(idx + 1) * stepc;
        float dl = fmaf(far, tl, NEARV * (1.0f - tl));
        float dh = fmaf(far, th, NEARV * (1.0f - th));
        float fl = sigmoidf_(zl) - 0.5f;
        float fh = sigmoidf_(zh) - 0.5f;

#pragma unroll 1
        for (int it = 0; it < NSECANT; it++) {
            float den = fh - fl;
            if (fabsf(den) < EPSV) den = EPSV;
            const float dm = dl - __fdividef(fl * (dh - dl), den);
            float zm;
            if (ovf) {
                zm = zfull(dm, rx, ry, rz, sW1[0], sW1[1], sW1[2],
                           sA, sV, b2v);
            } else {
                zm = zeval_bracket(dm, aL, bL, cnt, negmask, col);
            }
            const float fm = sigmoidf_(zm) - 0.5f;
            if (fm < 0.0f) { dl = dm; fl = fm; }
            else           { dh = dm; fh = fm; }
        }
        float den = fh - fl;
        if (fabsf(den) < EPSV) den = EPSV;
        dpred = dl - __fdividef(fl * (dh - dl), den);
        float zs;
        if (ovf) {
            zs = zfull(dpred, rx, ry, rz, sW1[0], sW1[1], sW1[2],
                       sA, sV, b2v);
        } else {
            zs = zeval_bracket(dpred, aL, bL, cnt, negmask, col);
        }
        osurf = sigmoidf_(zs);
    }

    out[p] = dpred;
    out[P + p] = osurf;
}

extern "C" void kernel_launch(void* const* d_in, const int* in_sizes, int n_in,
                              void* d_out, int out_size)
{
    const float* cam  = (const float*)d_in[0];
    const float* dirs = (const float*)d_in[1];
    const float* W1   = (const float*)d_in[2];
    const float* b1   = (const float*)d_in[3];
    const float* W2   = (const float*)d_in[4];
    const float* b2   = (const float*)d_in[5];
    float* out = (float*)d_out;

    const int P = in_sizes[1] / 3;
    int blocks = (P + THREADS - 1) / THREADS;
    if (blocks < 1) blocks = 1;
    unisurf_kernel<<<blocks, THREADS>>>(cam, dirs, W1, b1, W2, b2, out, P);
}